// round 16
// baseline (speedup 1.0000x reference)
#include <cuda_runtime.h>
#include <cuda_bf16.h>
#include <math.h>

#define BATCH 8
#define DMODEL 256
#define HEADS 8
#define DK 32
#define NPIX 1024
// 1/sqrt(32) * log2(e)
#define QK_SCALE_L2E 0.25501394102820344f

// ---------------- scratch ----------------
__device__ float g_part[1024];
__device__ unsigned char g_xa[64 * 65536];        // 64 m-tile A images (swizzled bf16), 4MB
__device__ unsigned char g_wt[16 * 32768];        // 16 weight tiles [64x256] bf16, swizzled
__device__ unsigned short g_q[64 * NPIX * DK];    // f16, pre-scaled by log2e/sqrt(dk)
__device__ unsigned short g_k[64 * NPIX * DK];    // f16
__device__ unsigned short g_v[64 * NPIX * DK];    // f16
__device__ unsigned g_po[2 * 64 * NPIX * 16];     // split-KV partial O, bf16x2 packed
__device__ float g_pl[2 * 64 * NPIX];             // split-KV partial row sums

// ---------------- helpers ----------------
__device__ __forceinline__ unsigned smem_u32(const void* p) {
    unsigned a;
    asm("{ .reg .u64 t; cvta.to.shared.u64 t, %1; cvt.u32.u64 %0, t; }" : "=r"(a) : "l"(p));
    return a;
}
__device__ __forceinline__ unsigned pack_bf16(float a, float b) {
    unsigned r;
    asm("cvt.rn.bf16x2.f32 %0, %1, %2;" : "=r"(r) : "f"(b), "f"(a));
    return r;   // lo=a, hi=b
}
__device__ __forceinline__ float2 bf2f(unsigned u) {
    float2 r;
    r.x = __uint_as_float(u << 16);
    r.y = __uint_as_float(u & 0xFFFF0000u);
    return r;
}
__device__ __forceinline__ unsigned pack_f16(float lo, float hi) {
    unsigned r;
    asm("cvt.rn.f16x2.f32 %0, %1, %2;" : "=r"(r) : "f"(hi), "f"(lo));
    return r;
}
__device__ __forceinline__ unsigned ex2x2(unsigned h2) {
    unsigned r;
    asm("ex2.approx.f16x2 %0, %1;" : "=r"(r) : "r"(h2));
    return r;
}
__device__ __forceinline__ unsigned sw512(unsigned row, unsigned chunk) {
    return row * 512u + (((chunk & ~7u) | ((chunk ^ row) & 7u)) << 4);
}
__device__ __forceinline__ unsigned kvaddr(unsigned row, unsigned c) {
    return row * 128u + (((c ^ (row & 7u))) << 4);
}
__device__ __forceinline__ void ldsm4(unsigned* r, unsigned a) {
    asm volatile("ldmatrix.sync.aligned.m8n8.x4.shared.b16 {%0,%1,%2,%3}, [%4];"
        : "=r"(r[0]), "=r"(r[1]), "=r"(r[2]), "=r"(r[3]) : "r"(a));
}
__device__ __forceinline__ void ldsm4t(unsigned* r, unsigned a) {
    asm volatile("ldmatrix.sync.aligned.m8n8.x4.trans.shared.b16 {%0,%1,%2,%3}, [%4];"
        : "=r"(r[0]), "=r"(r[1]), "=r"(r[2]), "=r"(r[3]) : "r"(a));
}
__device__ __forceinline__ void mma16816(float* c, const unsigned* a, const unsigned* b) {
    asm volatile("mma.sync.aligned.m16n8k16.row.col.f32.bf16.bf16.f32 "
        "{%0,%1,%2,%3}, {%4,%5,%6,%7}, {%8,%9}, {%0,%1,%2,%3};"
        : "+f"(c[0]), "+f"(c[1]), "+f"(c[2]), "+f"(c[3])
        : "r"(a[0]), "r"(a[1]), "r"(a[2]), "r"(a[3]), "r"(b[0]), "r"(b[1]));
}
__device__ __forceinline__ void mma16816h(float* c, const unsigned* a, const unsigned* b) {
    asm volatile("mma.sync.aligned.m16n8k16.row.col.f32.f16.f16.f32 "
        "{%0,%1,%2,%3}, {%4,%5,%6,%7}, {%8,%9}, {%0,%1,%2,%3};"
        : "+f"(c[0]), "+f"(c[1]), "+f"(c[2]), "+f"(c[3])
        : "r"(a[0]), "r"(a[1]), "r"(a[2]), "r"(a[3]), "r"(b[0]), "r"(b[1]));
}
// f16 in, f16 accumulate: D/C = 2 x f16x2 regs (layout == ex2/PV-A-frag input)
__device__ __forceinline__ void mma16816hh(unsigned* d, const unsigned* a, const unsigned* b) {
    asm volatile("mma.sync.aligned.m16n8k16.row.col.f16.f16.f16.f16 "
        "{%0,%1}, {%2,%3,%4,%5}, {%6,%7}, {%0,%1};"
        : "+r"(d[0]), "+r"(d[1])
        : "r"(a[0]), "r"(a[1]), "r"(a[2]), "r"(a[3]), "r"(b[0]), "r"(b[1]));
}
__device__ __forceinline__ void cp_async16(unsigned dst, const void* src) {
    asm volatile("cp.async.cg.shared.global [%0], [%1], 16;" :: "r"(dst), "l"(src));
}

// ---------------- LayerNorm stats + weight pre-convert (merged launch) ----------------
__global__ void ln_part(const float* __restrict__ x,
                        const float* __restrict__ Wq, const float* __restrict__ Wk,
                        const float* __restrict__ Wv, const float* __restrict__ Wo) {
    int bp = blockIdx.x;
    if (bp >= 512) {
        int t = (bp - 512) * 256 + threadIdx.x;
        int tile = t >> 11, row = (t >> 5) & 63, chunk = t & 31;
        int mat = tile >> 2, r64 = tile & 3;
        const float* W = (mat == 0) ? Wq : (mat == 1) ? Wk : (mat == 2) ? Wv : Wo;
        const float4* src = (const float4*)(W + (size_t)(r64 * 64 + row) * 256 + chunk * 8);
        float4 a = src[0], b = src[1];
        uint4 u = make_uint4(pack_bf16(a.x, a.y), pack_bf16(a.z, a.w),
                             pack_bf16(b.x, b.y), pack_bf16(b.z, b.w));
        *(uint4*)(g_wt + (size_t)tile * 32768 + sw512(row, chunk)) = u;
        return;
    }
    int b = bp >> 6, s = bp & 63;
    const float4* xb = (const float4*)(x + (size_t)b * DMODEL * NPIX) + s * 1024;
    int t = threadIdx.x;
    float sm = 0.f, ss = 0.f;
    #pragma unroll
    for (int j = 0; j < 4; j++) {
        float4 v = xb[t + j * 256];
        sm += v.x + v.y + v.z + v.w;
        ss += v.x * v.x + v.y * v.y + v.z * v.z + v.w * v.w;
    }
    __shared__ float s0[256], s1[256];
    s0[t] = sm; s1[t] = ss;
    __syncthreads();
    for (int off = 128; off > 0; off >>= 1) {
        if (t < off) { s0[t] += s0[t + off]; s1[t] += s1[t + off]; }
        __syncthreads();
    }
    if (t == 0) { g_part[bp * 2] = s0[0]; g_part[bp * 2 + 1] = s1[0]; }
}

// ---------------- normalize x -> swizzled A-tile images (ln_final merged in) ----------------
__global__ void norm_x2(const float* __restrict__ x) {
    extern __shared__ char sm[];
    __shared__ float r0s[256], r1s[256], s_mu, s_rs;
    int mt = blockIdx.x >> 3, rq = blockIdx.x & 7;
    int b = mt >> 3, n0 = (mt & 7) * 128 + rq * 16;
    int t = threadIdx.x;

    r0s[t] = (t < 64) ? g_part[(b * 64 + t) * 2]     : 0.f;
    r1s[t] = (t < 64) ? g_part[(b * 64 + t) * 2 + 1] : 0.f;
    __syncthreads();
    for (int off = 32; off > 0; off >>= 1) {
        if (t < off) { r0s[t] += r0s[t + off]; r1s[t] += r1s[t + off]; }
        __syncthreads();
    }
    if (t == 0) {
        const float invN = 1.f / (float)(DMODEL * NPIX);
        float mean = r0s[0] * invN;
        float var  = r1s[0] * invN - mean * mean;
        s_mu = mean;
        s_rs = rsqrtf(var + 1e-5f);
    }
    __syncthreads();
    float mu = s_mu, rs = s_rs;

    #pragma unroll
    for (int i = 0; i < 2; i++) {
        int lin = t + i * 256;
        int n4 = lin >> 7, cp = lin & 127;
        const float* r0 = x + ((size_t)b * 256 + 2 * cp) * 1024 + n0 + n4 * 4;
        float4 a = *(const float4*)r0;
        float4 c = *(const float4*)(r0 + 1024);
        a.x = (a.x - mu) * rs; a.y = (a.y - mu) * rs;
        a.z = (a.z - mu) * rs; a.w = (a.w - mu) * rs;
        c.x = (c.x - mu) * rs; c.y = (c.y - mu) * rs;
        c.z = (c.z - mu) * rs; c.w = (c.w - mu) * rs;
        unsigned u0 = pack_bf16(a.x, c.x), u1 = pack_bf16(a.y, c.y);
        unsigned u2 = pack_bf16(a.z, c.z), u3 = pack_bf16(a.w, c.w);
        int cl = cp >> 2;
        int off = (cp & 3) * 4;
        #pragma unroll
        for (int j = 0; j < 4; j++) {
            int row = n4 * 4 + j;
            unsigned gr = (cl & ~7) | ((cl ^ row) & 7);
            unsigned addr = row * 512u + gr * 16u + off;
            unsigned v = (j == 0) ? u0 : (j == 1) ? u1 : (j == 2) ? u2 : u3;
            *(unsigned*)(sm + addr) = v;
        }
    }
    __syncthreads();
    unsigned char* dst = g_xa + (size_t)mt * 65536 + rq * 16 * 512;
    #pragma unroll
    for (int i = 0; i < 2; i++) {
        int lin = t + i * 256;
        int row = lin >> 5, c16 = lin & 31;
        uint4 u = *(uint4*)(sm + row * 512 + c16 * 16);
        *(uint4*)(dst + row * 512 + c16 * 16) = u;
    }
}

// ---------------- QKV projection: 128 thr, warps 2m x 2n, 2-stage ring ----------------
// grid (64, 12). Stage = 16KB A panel + 8KB B panel = 24KB; 2 stages = 48KB.
__global__ void __launch_bounds__(128, 4) qkv_tc(const float* __restrict__ bq,
                                                 const float* __restrict__ bk,
                                                 const float* __restrict__ bv) {
    extern __shared__ char sm[];
    int tid = threadIdx.x, w = tid >> 5, l = tid & 31;
    int m0 = blockIdx.x * 128, b = m0 >> 10, n0 = m0 & 1023;
    int sel = blockIdx.y >> 2, og = (blockIdx.y & 3) * 64;
    const float* bias = (sel == 0) ? bq : (sel == 1) ? bk : bv;
    unsigned sbase = smem_u32(sm);
    const char* asrc = (const char*)g_xa + (size_t)blockIdx.x * 65536;
    const char* wsrc = (const char*)g_wt + (size_t)blockIdx.y * 32768;

    #pragma unroll
    for (int p = 0; p < 2; p++) {
        unsigned st = sbase + p * 24576;
        #pragma unroll
        for (int i = 0; i < 8; i++) {
            int lin = tid + i * 128;
            cp_async16(st + lin * 16, asrc + (lin >> 3) * 512 + p * 128 + (lin & 7) * 16);
        }
        #pragma unroll
        for (int i = 0; i < 4; i++) {
            int lin = tid + i * 128;
            cp_async16(st + 16384 + lin * 16, wsrc + (lin >> 3) * 512 + p * 128 + (lin & 7) * 16);
        }
        asm volatile("cp.async.commit_group;" ::: "memory");
    }

    int wm = (w & 1) * 64, wn = (w >> 1) * 32;
    float acc[4][4][4] = {};
    for (int p = 0; p < 4; p++) {
        if (p < 3) asm volatile("cp.async.wait_group 1;" ::: "memory");
        else       asm volatile("cp.async.wait_group 0;" ::: "memory");
        __syncthreads();
        unsigned ab = sbase + (p & 1) * 24576, bb = ab + 16384;
        #pragma unroll
        for (int ks = 0; ks < 4; ks++) {
            unsigned af[4][4];
            #pragma unroll
            for (int mt = 0; mt < 4; mt++)
                ldsm4(af[mt], ab + kvaddr(wm + mt * 16 + (l & 15), ks * 2 + (l >> 4)));
            #pragma unroll
            for (int np = 0; np < 2; np++) {
                unsigned bf[4];
                ldsm4(bf, bb + kvaddr(wn + np * 16 + (l & 7) + ((l >> 4) << 3),
                                      ks * 2 + ((l >> 3) & 1)));
                #pragma unroll
                for (int mt = 0; mt < 4; mt++) {
                    mma16816(acc[mt][np * 2],     af[mt], bf);
                    mma16816(acc[mt][np * 2 + 1], af[mt], bf + 2);
                }
            }
        }
        if (p < 2) {
            __syncthreads();
            int pf = p + 2;
            unsigned st = sbase + (p & 1) * 24576;
            #pragma unroll
            for (int i = 0; i < 8; i++) {
                int lin = tid + i * 128;
                cp_async16(st + lin * 16, asrc + (lin >> 3) * 512 + pf * 128 + (lin & 7) * 16);
            }
            #pragma unroll
            for (int i = 0; i < 4; i++) {
                int lin = tid + i * 128;
                cp_async16(st + 16384 + lin * 16, wsrc + (lin >> 3) * 512 + pf * 128 + (lin & 7) * 16);
            }
            asm volatile("cp.async.commit_group;" ::: "memory");
        }
    }
    float vs = (sel == 0) ? QK_SCALE_L2E : 1.f;
    unsigned short* dst = (sel == 0) ? g_q : (sel == 1) ? g_k : g_v;
    #pragma unroll
    for (int mt = 0; mt < 4; mt++)
        #pragma unroll
        for (int nt = 0; nt < 4; nt++) {
            int oc = og + wn + nt * 8 + (l & 3) * 2;
            int head = oc >> 5, d = oc & 31;
            float b0 = bias[oc], b1 = bias[oc + 1];
            int n = n0 + wm + mt * 16 + (l >> 2);
            size_t base = ((size_t)(b * 8 + head) * 1024);
            float p00 = (acc[mt][nt][0] + b0) * vs, p01 = (acc[mt][nt][1] + b1) * vs;
            float p10 = (acc[mt][nt][2] + b0) * vs, p11 = (acc[mt][nt][3] + b1) * vs;
            *(unsigned*)(dst + (base + n) * 32 + d)     = pack_f16(p00, p01);
            *(unsigned*)(dst + (base + n + 8) * 32 + d) = pack_f16(p10, p11);
        }
}

// ---------------- attention: split-KV x2, 128 thr, 2-stage ring, f16 S accum ----------------
// grid (16, 64): x = qtile*2 + split. Each block: 128 q-rows x 512 keys. 5 blocks/SM.
__global__ void __launch_bounds__(128, 5) attn_tc() {
    extern __shared__ char sm[];
    int tid = threadIdx.x, w = tid >> 5, l = tid & 31;
    int bh = blockIdx.y;
    int split = blockIdx.x & 1, qtile = blockIdx.x >> 1;
    int q0 = qtile * 128;
    unsigned sbase = smem_u32(sm);

    size_t kvbase = (size_t)bh * 1024 + split * 512;
    const uint4* ksrc = (const uint4*)(g_k + kvbase * 32);
    const uint4* vsrc = (const uint4*)(g_v + kvbase * 32);
    int row = tid;

    #pragma unroll
    for (int kt = 0; kt < 2; kt++) {
        unsigned st = sbase + kt * 16384;
        #pragma unroll
        for (int c = 0; c < 4; c++) {
            cp_async16(st + kvaddr(row, c),     ksrc + (kt * 128 + row) * 4 + c);
            cp_async16(st + kvaddr(row, c + 4), vsrc + (kt * 128 + row) * 4 + c);
        }
        asm volatile("cp.async.commit_group;" ::: "memory");
    }

    // Q fragments (f16), 2 m16 streams per warp (rows w*32..w*32+31)
    unsigned qa[2][2][4];
    {
        const unsigned short* qb = g_q + (size_t)(bh * 1024 + q0) * 32;
        int r0 = w * 32 + (l >> 2);
        #pragma unroll
        for (int mt = 0; mt < 2; mt++)
            #pragma unroll
            for (int ks = 0; ks < 2; ks++)
                #pragma unroll
                for (int j = 0; j < 4; j++)
                    qa[mt][ks][j] = *(const unsigned*)(qb
                        + (size_t)(r0 + mt * 16 + (j & 1) * 8) * 32
                        + ks * 16 + (l & 3) * 2 + ((j >> 1) << 3));
    }

    float o[2][4][4] = {};
    float osum[2][4] = {};
    unsigned bs0 = (l < 4) ? 0x3C003C00u : 0u;
    unsigned bsum[2] = {bs0, bs0};

    for (int kt = 0; kt < 4; kt++) {
        if (kt < 3) asm volatile("cp.async.wait_group 1;" ::: "memory");
        else        asm volatile("cp.async.wait_group 0;" ::: "memory");
        __syncthreads();
        unsigned kb = sbase + (kt & 1) * 16384;

        #pragma unroll
        for (int np = 0; np < 8; np++) {
            unsigned kf[2][4], vf[2][4];
            #pragma unroll
            for (int ks = 0; ks < 2; ks++)
                ldsm4(kf[ks], kb + kvaddr(np * 16 + (l & 7) + ((l >> 4) << 3),
                                          ks * 2 + ((l >> 3) & 1)));
            #pragma unroll
            for (int np2 = 0; np2 < 2; np2++)
                ldsm4t(vf[np2], kb + kvaddr(np * 16 + (l & 15),
                                            4 + np2 * 2 + (l >> 4)));
            #pragma unroll
            for (int mt = 0; mt < 2; mt++) {
                unsigned s0[2] = {0u, 0u}, s1[2] = {0u, 0u};
                #pragma unroll
                for (int ks = 0; ks < 2; ks++) {
                    mma16816hh(s0, qa[mt][ks], kf[ks]);
                    mma16816hh(s1, qa[mt][ks], kf[ks] + 2);
                }
                unsigned pp[4];
                pp[0] = ex2x2(s0[0]);
                pp[1] = ex2x2(s0[1]);
                pp[2] = ex2x2(s1[0]);
                pp[3] = ex2x2(s1[1]);
                #pragma unroll
                for (int np2 = 0; np2 < 2; np2++) {
                    mma16816h(o[mt][np2 * 2],     pp, vf[np2]);
                    mma16816h(o[mt][np2 * 2 + 1], pp, vf[np2] + 2);
                }
                mma16816h(osum[mt], pp, bsum);
            }
        }
        if (kt < 2) {
            __syncthreads();   // stage (kt&1) fully consumed by all warps
            int pf = kt + 2;
            unsigned st = sbase + (kt & 1) * 16384;
            #pragma unroll
            for (int c = 0; c < 4; c++) {
                cp_async16(st + kvaddr(row, c),     ksrc + (pf * 128 + row) * 4 + c);
                cp_async16(st + kvaddr(row, c + 4), vsrc + (pf * 128 + row) * 4 + c);
            }
            asm volatile("cp.async.commit_group;" ::: "memory");
        }
    }

    size_t obase = (size_t)(split * 64 + bh) * 1024;
    #pragma unroll
    for (int mt = 0; mt < 2; mt++) {
        int qr = q0 + w * 32 + mt * 16 + (l >> 2);
        #pragma unroll
        for (int nt = 0; nt < 4; nt++) {
            g_po[(obase + qr) * 16 + nt * 4 + (l & 3)]     = pack_bf16(o[mt][nt][0], o[mt][nt][1]);
            g_po[(obase + qr + 8) * 16 + nt * 4 + (l & 3)] = pack_bf16(o[mt][nt][2], o[mt][nt][3]);
        }
        if ((l & 3) == 0) {
            g_pl[obase + qr]     = osum[mt][0];
            g_pl[obase + qr + 8] = osum[mt][2];
        }
    }
}

// ---------------- output projection + bias + residual (combine fused) ----------------
__global__ void out_tc(const float* __restrict__ x, const float* __restrict__ bo,
                       float* __restrict__ out) {
    extern __shared__ char sm[];
    int tid = threadIdx.x, w = tid >> 5, l = tid & 31;
    int m0 = blockIdx.x * 128, o0 = blockIdx.y * 64;
    unsigned ab = smem_u32(sm), bb = ab + 65536;

    {
        const char* wsrc = (const char*)g_wt + (size_t)(12 + blockIdx.y) * 32768;
        #pragma unroll
        for (int i = 0; i < 8; i++) {
            int lin = tid + i * 256;
            cp_async16(bb + lin * 16, wsrc + lin * 16);
        }
        asm volatile("cp.async.commit_group;" ::: "memory");
    }
    #pragma unroll 4
    for (int i = 0; i < 16; i++) {
        int lin = tid + i * 256;
        int rowA = lin >> 5, chunk = lin & 31;
        int m = m0 + rowA;
        int b = m >> 10, n = m & 1023;
        int h = chunk >> 2;
        size_t i0 = (size_t)(b * 8 + h) * 1024 + n;
        size_t i1 = i0 + 65536;
        uint4 p0 = *(const uint4*)(g_po + i0 * 16 + (chunk & 3) * 4);
        uint4 p1 = *(const uint4*)(g_po + i1 * 16 + (chunk & 3) * 4);
        float inv = 1.f / (g_pl[i0] + g_pl[i1]);
        float2 a0, a1;
        uint4 u;
        a0 = bf2f(p0.x); a1 = bf2f(p1.x);
        u.x = pack_bf16((a0.x + a1.x) * inv, (a0.y + a1.y) * inv);
        a0 = bf2f(p0.y); a1 = bf2f(p1.y);
        u.y = pack_bf16((a0.x + a1.x) * inv, (a0.y + a1.y) * inv);
        a0 = bf2f(p0.z); a1 = bf2f(p1.z);
        u.z = pack_bf16((a0.x + a1.x) * inv, (a0.y + a1.y) * inv);
        a0 = bf2f(p0.w); a1 = bf2f(p1.w);
        u.w = pack_bf16((a0.x + a1.x) * inv, (a0.y + a1.y) * inv);
        *(uint4*)(sm + sw512(rowA, chunk)) = u;
    }
    asm volatile("cp.async.wait_group 0;" ::: "memory");
    __syncthreads();

    int wm = (w & 3) * 32, wn = (w >> 2) * 32;
    float acc[2][4][4] = {};
    #pragma unroll
    for (int ks = 0; ks < 16; ks++) {
        unsigned af[2][4];
        #pragma unroll
        for (int mt = 0; mt < 2; mt++)
            ldsm4(af[mt], ab + sw512(wm + mt * 16 + (l & 15), ks * 2 + (l >> 4)));
        #pragma unroll
        for (int np = 0; np < 2; np++) {
            unsigned bf[4];
            ldsm4(bf, bb + sw512(wn + np * 16 + (l & 7) + ((l >> 4) << 3),
                                 ks * 2 + ((l >> 3) & 1)));
            #pragma unroll
            for (int mt = 0; mt < 2; mt++) {
                mma16816(acc[mt][np * 2],     af[mt], bf);
                mma16816(acc[mt][np * 2 + 1], af[mt], bf + 2);
            }
        }
    }
    #pragma unroll
    for (int mt = 0; mt < 2; mt++)
        #pragma unroll
        for (int nt = 0; nt < 4; nt++) {
            int col = o0 + wn + nt * 8 + (l & 3) * 2;
            int m = m0 + wm + mt * 16 + (l >> 2);
            float b0 = bo[col], b1 = bo[col + 1];
            size_t i0 = (size_t)m * 256 + col;
            size_t i1 = (size_t)(m + 8) * 256 + col;
            float2 r0, r1;
            r0.x = acc[mt][nt][0] + b0 + x[i0];
            r0.y = acc[mt][nt][1] + b1 + x[i0 + 1];
            r1.x = acc[mt][nt][2] + b0 + x[i1];
            r1.y = acc[mt][nt][3] + b1 + x[i1 + 1];
            *(float2*)(out + i0) = r0;
            *(float2*)(out + i1) = r1;
        }
}

// ---------------- launch ----------------
extern "C" void kernel_launch(void* const* d_in, const int* in_sizes, int n_in,
                              void* d_out, int out_size) {
    const float* x  = (const float*)d_in[0];
    const float* Wq = (const float*)d_in[1];
    const float* bq = (const float*)d_in[2];
    const float* Wk = (const float*)d_in[3];
    const float* bk = (const float*)d_in[4];
    const float* Wv = (const float*)d_in[5];
    const float* bv = (const float*)d_in[6];
    const float* Wo = (const float*)d_in[7];
    const float* bo = (const float*)d_in[8];
    float* out = (float*)d_out;

    const int SMEM_QKV  = 49152;   // 2 stages x 24KB
    const int SMEM_GEMM = 98304;   // 64KB A + 32KB B (out_tc)
    const int SMEM_ATTN = 32768;   // 2 stages x 16KB
    cudaFuncSetAttribute(qkv_tc,  cudaFuncAttributeMaxDynamicSharedMemorySize, SMEM_QKV);
    cudaFuncSetAttribute(attn_tc, cudaFuncAttributeMaxDynamicSharedMemorySize, SMEM_ATTN);
    cudaFuncSetAttribute(out_tc,  cudaFuncAttributeMaxDynamicSharedMemorySize, SMEM_GEMM);

    ln_part<<<640, 256>>>(x, Wq, Wk, Wv, Wo);
    norm_x2<<<512, 256, 8192>>>(x);
    qkv_tc<<<dim3(64, 12), 128, SMEM_QKV>>>(bq, bk, bv);
    attn_tc<<<dim3(16, 64), 128, SMEM_ATTN>>>();
    out_tc<<<dim3(64, 4), 256, SMEM_GEMM>>>(x, bo, out);
}

// round 17
// speedup vs baseline: 1.0407x; 1.0407x over previous
#include <cuda_runtime.h>
#include <cuda_bf16.h>
#include <math.h>

#define BATCH 8
#define DMODEL 256
#define HEADS 8
#define DK 32
#define NPIX 1024
// 1/sqrt(32) * log2(e)
#define QK_SCALE_L2E 0.25501394102820344f

// ---------------- scratch ----------------
__device__ float g_part[1024];
__device__ unsigned char g_xa[64 * 65536];        // 64 m-tile A images (swizzled bf16), 4MB
__device__ unsigned char g_wt[16 * 32768];        // 16 weight tiles [64x256] bf16, swizzled
__device__ unsigned short g_q[64 * NPIX * DK];    // f16, pre-scaled by log2e/sqrt(dk)
__device__ unsigned short g_k[64 * NPIX * DK];    // f16
__device__ unsigned short g_v[64 * NPIX * DK];    // f16
__device__ unsigned g_po[2 * 64 * NPIX * 16];     // split-KV partial O, bf16x2 packed
__device__ float g_pl[2 * 64 * NPIX];             // split-KV partial row sums

// ---------------- helpers ----------------
__device__ __forceinline__ unsigned smem_u32(const void* p) {
    unsigned a;
    asm("{ .reg .u64 t; cvta.to.shared.u64 t, %1; cvt.u32.u64 %0, t; }" : "=r"(a) : "l"(p));
    return a;
}
__device__ __forceinline__ unsigned pack_bf16(float a, float b) {
    unsigned r;
    asm("cvt.rn.bf16x2.f32 %0, %1, %2;" : "=r"(r) : "f"(b), "f"(a));
    return r;   // lo=a, hi=b
}
__device__ __forceinline__ float2 bf2f(unsigned u) {
    float2 r;
    r.x = __uint_as_float(u << 16);
    r.y = __uint_as_float(u & 0xFFFF0000u);
    return r;
}
__device__ __forceinline__ unsigned pack_f16(float lo, float hi) {
    unsigned r;
    asm("cvt.rn.f16x2.f32 %0, %1, %2;" : "=r"(r) : "f"(hi), "f"(lo));
    return r;
}
__device__ __forceinline__ unsigned ex2x2(unsigned h2) {
    unsigned r;
    asm("ex2.approx.f16x2 %0, %1;" : "=r"(r) : "r"(h2));
    return r;
}
__device__ __forceinline__ unsigned sw512(unsigned row, unsigned chunk) {
    return row * 512u + (((chunk & ~7u) | ((chunk ^ row) & 7u)) << 4);
}
__device__ __forceinline__ unsigned kvaddr(unsigned row, unsigned c) {
    return row * 128u + (((c ^ (row & 7u))) << 4);
}
__device__ __forceinline__ void ldsm4(unsigned* r, unsigned a) {
    asm volatile("ldmatrix.sync.aligned.m8n8.x4.shared.b16 {%0,%1,%2,%3}, [%4];"
        : "=r"(r[0]), "=r"(r[1]), "=r"(r[2]), "=r"(r[3]) : "r"(a));
}
__device__ __forceinline__ void ldsm4t(unsigned* r, unsigned a) {
    asm volatile("ldmatrix.sync.aligned.m8n8.x4.trans.shared.b16 {%0,%1,%2,%3}, [%4];"
        : "=r"(r[0]), "=r"(r[1]), "=r"(r[2]), "=r"(r[3]) : "r"(a));
}
__device__ __forceinline__ void mma16816(float* c, const unsigned* a, const unsigned* b) {
    asm volatile("mma.sync.aligned.m16n8k16.row.col.f32.bf16.bf16.f32 "
        "{%0,%1,%2,%3}, {%4,%5,%6,%7}, {%8,%9}, {%0,%1,%2,%3};"
        : "+f"(c[0]), "+f"(c[1]), "+f"(c[2]), "+f"(c[3])
        : "r"(a[0]), "r"(a[1]), "r"(a[2]), "r"(a[3]), "r"(b[0]), "r"(b[1]));
}
__device__ __forceinline__ void mma16816h(float* c, const unsigned* a, const unsigned* b) {
    asm volatile("mma.sync.aligned.m16n8k16.row.col.f32.f16.f16.f32 "
        "{%0,%1,%2,%3}, {%4,%5,%6,%7}, {%8,%9}, {%0,%1,%2,%3};"
        : "+f"(c[0]), "+f"(c[1]), "+f"(c[2]), "+f"(c[3])
        : "r"(a[0]), "r"(a[1]), "r"(a[2]), "r"(a[3]), "r"(b[0]), "r"(b[1]));
}
// f16 in, f16 accumulate: D/C = 2 x f16x2 regs (layout == ex2/PV-A-frag input)
__device__ __forceinline__ void mma16816hh(unsigned* d, const unsigned* a, const unsigned* b) {
    asm volatile("mma.sync.aligned.m16n8k16.row.col.f16.f16.f16.f16 "
        "{%0,%1}, {%2,%3,%4,%5}, {%6,%7}, {%0,%1};"
        : "+r"(d[0]), "+r"(d[1])
        : "r"(a[0]), "r"(a[1]), "r"(a[2]), "r"(a[3]), "r"(b[0]), "r"(b[1]));
}
__device__ __forceinline__ void cp_async16(unsigned dst, const void* src) {
    asm volatile("cp.async.cg.shared.global [%0], [%1], 16;" :: "r"(dst), "l"(src));
}

// ---------------- LayerNorm stats + weight pre-convert (merged launch) ----------------
__global__ void ln_part(const float* __restrict__ x,
                        const float* __restrict__ Wq, const float* __restrict__ Wk,
                        const float* __restrict__ Wv, const float* __restrict__ Wo) {
    int bp = blockIdx.x;
    if (bp >= 512) {
        int t = (bp - 512) * 256 + threadIdx.x;
        int tile = t >> 11, row = (t >> 5) & 63, chunk = t & 31;
        int mat = tile >> 2, r64 = tile & 3;
        const float* W = (mat == 0) ? Wq : (mat == 1) ? Wk : (mat == 2) ? Wv : Wo;
        const float4* src = (const float4*)(W + (size_t)(r64 * 64 + row) * 256 + chunk * 8);
        float4 a = src[0], b = src[1];
        uint4 u = make_uint4(pack_bf16(a.x, a.y), pack_bf16(a.z, a.w),
                             pack_bf16(b.x, b.y), pack_bf16(b.z, b.w));
        *(uint4*)(g_wt + (size_t)tile * 32768 + sw512(row, chunk)) = u;
        return;
    }
    int b = bp >> 6, s = bp & 63;
    const float4* xb = (const float4*)(x + (size_t)b * DMODEL * NPIX) + s * 1024;
    int t = threadIdx.x;
    float sm = 0.f, ss = 0.f;
    #pragma unroll
    for (int j = 0; j < 4; j++) {
        float4 v = xb[t + j * 256];
        sm += v.x + v.y + v.z + v.w;
        ss += v.x * v.x + v.y * v.y + v.z * v.z + v.w * v.w;
    }
    __shared__ float s0[256], s1[256];
    s0[t] = sm; s1[t] = ss;
    __syncthreads();
    for (int off = 128; off > 0; off >>= 1) {
        if (t < off) { s0[t] += s0[t + off]; s1[t] += s1[t + off]; }
        __syncthreads();
    }
    if (t == 0) { g_part[bp * 2] = s0[0]; g_part[bp * 2 + 1] = s1[0]; }
}

// ---------------- normalize x -> swizzled A-tile images (ln_final merged in) ----------------
__global__ void norm_x2(const float* __restrict__ x) {
    extern __shared__ char sm[];
    __shared__ float r0s[256], r1s[256], s_mu, s_rs;
    int mt = blockIdx.x >> 3, rq = blockIdx.x & 7;
    int b = mt >> 3, n0 = (mt & 7) * 128 + rq * 16;
    int t = threadIdx.x;

    r0s[t] = (t < 64) ? g_part[(b * 64 + t) * 2]     : 0.f;
    r1s[t] = (t < 64) ? g_part[(b * 64 + t) * 2 + 1] : 0.f;
    __syncthreads();
    for (int off = 32; off > 0; off >>= 1) {
        if (t < off) { r0s[t] += r0s[t + off]; r1s[t] += r1s[t + off]; }
        __syncthreads();
    }
    if (t == 0) {
        const float invN = 1.f / (float)(DMODEL * NPIX);
        float mean = r0s[0] * invN;
        float var  = r1s[0] * invN - mean * mean;
        s_mu = mean;
        s_rs = rsqrtf(var + 1e-5f);
    }
    __syncthreads();
    float mu = s_mu, rs = s_rs;

    #pragma unroll
    for (int i = 0; i < 2; i++) {
        int lin = t + i * 256;
        int n4 = lin >> 7, cp = lin & 127;
        const float* r0 = x + ((size_t)b * 256 + 2 * cp) * 1024 + n0 + n4 * 4;
        float4 a = *(const float4*)r0;
        float4 c = *(const float4*)(r0 + 1024);
        a.x = (a.x - mu) * rs; a.y = (a.y - mu) * rs;
        a.z = (a.z - mu) * rs; a.w = (a.w - mu) * rs;
        c.x = (c.x - mu) * rs; c.y = (c.y - mu) * rs;
        c.z = (c.z - mu) * rs; c.w = (c.w - mu) * rs;
        unsigned u0 = pack_bf16(a.x, c.x), u1 = pack_bf16(a.y, c.y);
        unsigned u2 = pack_bf16(a.z, c.z), u3 = pack_bf16(a.w, c.w);
        int cl = cp >> 2;
        int off = (cp & 3) * 4;
        #pragma unroll
        for (int j = 0; j < 4; j++) {
            int row = n4 * 4 + j;
            unsigned gr = (cl & ~7) | ((cl ^ row) & 7);
            unsigned addr = row * 512u + gr * 16u + off;
            unsigned v = (j == 0) ? u0 : (j == 1) ? u1 : (j == 2) ? u2 : u3;
            *(unsigned*)(sm + addr) = v;
        }
    }
    __syncthreads();
    unsigned char* dst = g_xa + (size_t)mt * 65536 + rq * 16 * 512;
    #pragma unroll
    for (int i = 0; i < 2; i++) {
        int lin = t + i * 256;
        int row = lin >> 5, c16 = lin & 31;
        uint4 u = *(uint4*)(sm + row * 512 + c16 * 16);
        *(uint4*)(dst + row * 512 + c16 * 16) = u;
    }
}

// ---------------- QKV projection: 128 thr, warps 2m x 2n, 2-stage ring ----------------
// grid (64, 12). Stage = 16KB A panel + 8KB B panel = 24KB; 2 stages = 48KB.
__global__ void __launch_bounds__(128, 4) qkv_tc(const float* __restrict__ bq,
                                                 const float* __restrict__ bk,
                                                 const float* __restrict__ bv) {
    extern __shared__ char sm[];
    int tid = threadIdx.x, w = tid >> 5, l = tid & 31;
    int m0 = blockIdx.x * 128, b = m0 >> 10, n0 = m0 & 1023;
    int sel = blockIdx.y >> 2, og = (blockIdx.y & 3) * 64;
    const float* bias = (sel == 0) ? bq : (sel == 1) ? bk : bv;
    unsigned sbase = smem_u32(sm);
    const char* asrc = (const char*)g_xa + (size_t)blockIdx.x * 65536;
    const char* wsrc = (const char*)g_wt + (size_t)blockIdx.y * 32768;

    #pragma unroll
    for (int p = 0; p < 2; p++) {
        unsigned st = sbase + p * 24576;
        #pragma unroll
        for (int i = 0; i < 8; i++) {
            int lin = tid + i * 128;
            cp_async16(st + lin * 16, asrc + (lin >> 3) * 512 + p * 128 + (lin & 7) * 16);
        }
        #pragma unroll
        for (int i = 0; i < 4; i++) {
            int lin = tid + i * 128;
            cp_async16(st + 16384 + lin * 16, wsrc + (lin >> 3) * 512 + p * 128 + (lin & 7) * 16);
        }
        asm volatile("cp.async.commit_group;" ::: "memory");
    }

    int wm = (w & 1) * 64, wn = (w >> 1) * 32;
    float acc[4][4][4] = {};
    for (int p = 0; p < 4; p++) {
        if (p < 3) asm volatile("cp.async.wait_group 1;" ::: "memory");
        else       asm volatile("cp.async.wait_group 0;" ::: "memory");
        __syncthreads();
        unsigned ab = sbase + (p & 1) * 24576, bb = ab + 16384;
        #pragma unroll
        for (int ks = 0; ks < 4; ks++) {
            unsigned af[4][4];
            #pragma unroll
            for (int mt = 0; mt < 4; mt++)
                ldsm4(af[mt], ab + kvaddr(wm + mt * 16 + (l & 15), ks * 2 + (l >> 4)));
            #pragma unroll
            for (int np = 0; np < 2; np++) {
                unsigned bf[4];
                ldsm4(bf, bb + kvaddr(wn + np * 16 + (l & 7) + ((l >> 4) << 3),
                                      ks * 2 + ((l >> 3) & 1)));
                #pragma unroll
                for (int mt = 0; mt < 4; mt++) {
                    mma16816(acc[mt][np * 2],     af[mt], bf);
                    mma16816(acc[mt][np * 2 + 1], af[mt], bf + 2);
                }
            }
        }
        if (p < 2) {
            __syncthreads();
            int pf = p + 2;
            unsigned st = sbase + (p & 1) * 24576;
            #pragma unroll
            for (int i = 0; i < 8; i++) {
                int lin = tid + i * 128;
                cp_async16(st + lin * 16, asrc + (lin >> 3) * 512 + pf * 128 + (lin & 7) * 16);
            }
            #pragma unroll
            for (int i = 0; i < 4; i++) {
                int lin = tid + i * 128;
                cp_async16(st + 16384 + lin * 16, wsrc + (lin >> 3) * 512 + pf * 128 + (lin & 7) * 16);
            }
            asm volatile("cp.async.commit_group;" ::: "memory");
        }
    }
    float vs = (sel == 0) ? QK_SCALE_L2E : 1.f;
    unsigned short* dst = (sel == 0) ? g_q : (sel == 1) ? g_k : g_v;
    #pragma unroll
    for (int mt = 0; mt < 4; mt++)
        #pragma unroll
        for (int nt = 0; nt < 4; nt++) {
            int oc = og + wn + nt * 8 + (l & 3) * 2;
            int head = oc >> 5, d = oc & 31;
            float b0 = bias[oc], b1 = bias[oc + 1];
            int n = n0 + wm + mt * 16 + (l >> 2);
            size_t base = ((size_t)(b * 8 + head) * 1024);
            float p00 = (acc[mt][nt][0] + b0) * vs, p01 = (acc[mt][nt][1] + b1) * vs;
            float p10 = (acc[mt][nt][2] + b0) * vs, p11 = (acc[mt][nt][3] + b1) * vs;
            *(unsigned*)(dst + (base + n) * 32 + d)     = pack_f16(p00, p01);
            *(unsigned*)(dst + (base + n + 8) * 32 + d) = pack_f16(p10, p11);
        }
}

// ---------------- attention: split-KV x2, 128 thr, 3-stage ring, f16 S accum (R15 best) ----------------
__global__ void __launch_bounds__(128, 4) attn_tc() {
    extern __shared__ char sm[];
    int tid = threadIdx.x, w = tid >> 5, l = tid & 31;
    int bh = blockIdx.y;
    int split = blockIdx.x & 1, qtile = blockIdx.x >> 1;
    int q0 = qtile * 128;
    unsigned sbase = smem_u32(sm);

    size_t kvbase = (size_t)bh * 1024 + split * 512;
    const uint4* ksrc = (const uint4*)(g_k + kvbase * 32);
    const uint4* vsrc = (const uint4*)(g_v + kvbase * 32);
    int row = tid;

    #pragma unroll
    for (int kt = 0; kt < 2; kt++) {
        unsigned st = sbase + kt * 16384;
        #pragma unroll
        for (int c = 0; c < 4; c++) {
            cp_async16(st + kvaddr(row, c),     ksrc + (kt * 128 + row) * 4 + c);
            cp_async16(st + kvaddr(row, c + 4), vsrc + (kt * 128 + row) * 4 + c);
        }
        asm volatile("cp.async.commit_group;" ::: "memory");
    }

    unsigned qa[2][2][4];
    {
        const unsigned short* qb = g_q + (size_t)(bh * 1024 + q0) * 32;
        int r0 = w * 32 + (l >> 2);
        #pragma unroll
        for (int mt = 0; mt < 2; mt++)
            #pragma unroll
            for (int ks = 0; ks < 2; ks++)
                #pragma unroll
                for (int j = 0; j < 4; j++)
                    qa[mt][ks][j] = *(const unsigned*)(qb
                        + (size_t)(r0 + mt * 16 + (j & 1) * 8) * 32
                        + ks * 16 + (l & 3) * 2 + ((j >> 1) << 3));
    }

    float o[2][4][4] = {};
    float osum[2][4] = {};
    unsigned bs0 = (l < 4) ? 0x3C003C00u : 0u;
    unsigned bsum[2] = {bs0, bs0};

    for (int kt = 0; kt < 4; kt++) {
        if (kt < 3) asm volatile("cp.async.wait_group 1;" ::: "memory");
        else        asm volatile("cp.async.wait_group 0;" ::: "memory");
        __syncthreads();
        if (kt < 2) {
            int pf = kt + 2;
            unsigned st = sbase + (pf % 3) * 16384;
            #pragma unroll
            for (int c = 0; c < 4; c++) {
                cp_async16(st + kvaddr(row, c),     ksrc + (pf * 128 + row) * 4 + c);
                cp_async16(st + kvaddr(row, c + 4), vsrc + (pf * 128 + row) * 4 + c);
            }
            asm volatile("cp.async.commit_group;" ::: "memory");
        }
        unsigned kb = sbase + (kt % 3) * 16384;

        #pragma unroll
        for (int np = 0; np < 8; np++) {
            unsigned kf[2][4], vf[2][4];
            #pragma unroll
            for (int ks = 0; ks < 2; ks++)
                ldsm4(kf[ks], kb + kvaddr(np * 16 + (l & 7) + ((l >> 4) << 3),
                                          ks * 2 + ((l >> 3) & 1)));
            #pragma unroll
            for (int np2 = 0; np2 < 2; np2++)
                ldsm4t(vf[np2], kb + kvaddr(np * 16 + (l & 15),
                                            4 + np2 * 2 + (l >> 4)));
            #pragma unroll
            for (int mt = 0; mt < 2; mt++) {
                unsigned s0[2] = {0u, 0u}, s1[2] = {0u, 0u};
                #pragma unroll
                for (int ks = 0; ks < 2; ks++) {
                    mma16816hh(s0, qa[mt][ks], kf[ks]);
                    mma16816hh(s1, qa[mt][ks], kf[ks] + 2);
                }
                unsigned pp[4];
                pp[0] = ex2x2(s0[0]);
                pp[1] = ex2x2(s0[1]);
                pp[2] = ex2x2(s1[0]);
                pp[3] = ex2x2(s1[1]);
                #pragma unroll
                for (int np2 = 0; np2 < 2; np2++) {
                    mma16816h(o[mt][np2 * 2],     pp, vf[np2]);
                    mma16816h(o[mt][np2 * 2 + 1], pp, vf[np2] + 2);
                }
                mma16816h(osum[mt], pp, bsum);
            }
        }
    }

    size_t obase = (size_t)(split * 64 + bh) * 1024;
    #pragma unroll
    for (int mt = 0; mt < 2; mt++) {
        int qr = q0 + w * 32 + mt * 16 + (l >> 2);
        #pragma unroll
        for (int nt = 0; nt < 4; nt++) {
            g_po[(obase + qr) * 16 + nt * 4 + (l & 3)]     = pack_bf16(o[mt][nt][0], o[mt][nt][1]);
            g_po[(obase + qr + 8) * 16 + nt * 4 + (l & 3)] = pack_bf16(o[mt][nt][2], o[mt][nt][3]);
        }
        if ((l & 3) == 0) {
            g_pl[obase + qr]     = osum[mt][0];
            g_pl[obase + qr + 8] = osum[mt][2];
        }
    }
}

// ---------------- output projection: 64-row m-tiles, A built once, 2 B-chunks ----------------
// grid (128, 2), 256 thr. A @0 (32KB, 64 rows), B @32768 (32KB, 64 rows), loop og 0..1.
__global__ void __launch_bounds__(256, 3) out_tc(const float* __restrict__ x,
                                                 const float* __restrict__ bo,
                                                 float* __restrict__ out) {
    extern __shared__ char sm[];
    int tid = threadIdx.x, w = tid >> 5, l = tid & 31;
    int m0 = blockIdx.x * 64;
    int byy = blockIdx.y;                  // column half: byy*128
    unsigned ab = smem_u32(sm), bb = ab + 32768;
    const char* wsrc = (const char*)g_wt + (size_t)(12 + byy * 2) * 32768;  // 64KB = 2 tiles

    // prefetch B chunk og=0 (first 32KB tile)
    #pragma unroll
    for (int i = 0; i < 8; i++) {
        int lin = tid + i * 256;
        cp_async16(bb + lin * 16, wsrc + lin * 16);
    }
    asm volatile("cp.async.commit_group;" ::: "memory");

    // A tile: 64 rows x 32 chunks, combine split-KV partials (built ONCE)
    #pragma unroll 4
    for (int i = 0; i < 8; i++) {
        int lin = tid + i * 256;
        int rowA = lin >> 5, chunk = lin & 31;
        int m = m0 + rowA;
        int b = m >> 10, n = m & 1023;
        int h = chunk >> 2;
        size_t i0 = (size_t)(b * 8 + h) * 1024 + n;
        size_t i1 = i0 + 65536;
        uint4 p0 = *(const uint4*)(g_po + i0 * 16 + (chunk & 3) * 4);
        uint4 p1 = *(const uint4*)(g_po + i1 * 16 + (chunk & 3) * 4);
        float inv = 1.f / (g_pl[i0] + g_pl[i1]);
        float2 a0, a1;
        uint4 u;
        a0 = bf2f(p0.x); a1 = bf2f(p1.x);
        u.x = pack_bf16((a0.x + a1.x) * inv, (a0.y + a1.y) * inv);
        a0 = bf2f(p0.y); a1 = bf2f(p1.y);
        u.y = pack_bf16((a0.x + a1.x) * inv, (a0.y + a1.y) * inv);
        a0 = bf2f(p0.z); a1 = bf2f(p1.z);
        u.z = pack_bf16((a0.x + a1.x) * inv, (a0.y + a1.y) * inv);
        a0 = bf2f(p0.w); a1 = bf2f(p1.w);
        u.w = pack_bf16((a0.x + a1.x) * inv, (a0.y + a1.y) * inv);
        *(uint4*)(sm + sw512(rowA, chunk)) = u;
    }
    asm volatile("cp.async.wait_group 0;" ::: "memory");
    __syncthreads();

    int wm = (w >> 1) * 16, wn = (w & 1) * 32;   // 4 m-warps x 2 n-warps (16x32 warp tile)
    #pragma unroll
    for (int og = 0; og < 2; og++) {
        if (og == 1) {
            __syncthreads();   // og0 B reads complete
            #pragma unroll
            for (int i = 0; i < 8; i++) {
                int lin = tid + i * 256;
                cp_async16(bb + lin * 16, wsrc + 32768 + lin * 16);
            }
            asm volatile("cp.async.commit_group;" ::: "memory");
            asm volatile("cp.async.wait_group 0;" ::: "memory");
            __syncthreads();
        }
        float acc[4][4] = {};
        #pragma unroll
        for (int ks = 0; ks < 16; ks++) {
            unsigned af[4];
            ldsm4(af, ab + sw512(wm + (l & 15), ks * 2 + (l >> 4)));
            #pragma unroll
            for (int np = 0; np < 2; np++) {
                unsigned bf[4];
                ldsm4(bf, bb + sw512(wn + np * 16 + (l & 7) + ((l >> 4) << 3),
                                     ks * 2 + ((l >> 3) & 1)));
                mma16816(acc[np * 2],     af, bf);
                mma16816(acc[np * 2 + 1], af, bf + 2);
            }
        }
        #pragma unroll
        for (int nt = 0; nt < 4; nt++) {
            int col = byy * 128 + og * 64 + wn + nt * 8 + (l & 3) * 2;
            int m = m0 + wm + (l >> 2);
            float b0 = bo[col], b1 = bo[col + 1];
            size_t i0 = (size_t)m * 256 + col;
            size_t i1 = (size_t)(m + 8) * 256 + col;
            float2 r0, r1;
            r0.x = acc[nt][0] + b0 + x[i0];
            r0.y = acc[nt][1] + b1 + x[i0 + 1];
            r1.x = acc[nt][2] + b0 + x[i1];
            r1.y = acc[nt][3] + b1 + x[i1 + 1];
            *(float2*)(out + i0) = r0;
            *(float2*)(out + i1) = r1;
        }
    }
}

// ---------------- launch ----------------
extern "C" void kernel_launch(void* const* d_in, const int* in_sizes, int n_in,
                              void* d_out, int out_size) {
    const float* x  = (const float*)d_in[0];
    const float* Wq = (const float*)d_in[1];
    const float* bq = (const float*)d_in[2];
    const float* Wk = (const float*)d_in[3];
    const float* bk = (const float*)d_in[4];
    const float* Wv = (const float*)d_in[5];
    const float* bv = (const float*)d_in[6];
    const float* Wo = (const float*)d_in[7];
    const float* bo = (const float*)d_in[8];
    float* out = (float*)d_out;

    const int SMEM_QKV  = 49152;   // 2 stages x 24KB
    const int SMEM_OUT  = 65536;   // A 32KB + B 32KB
    const int SMEM_ATTN = 49152;   // 3 stages x 16KB
    cudaFuncSetAttribute(qkv_tc,  cudaFuncAttributeMaxDynamicSharedMemorySize, SMEM_QKV);
    cudaFuncSetAttribute(attn_tc, cudaFuncAttributeMaxDynamicSharedMemorySize, SMEM_ATTN);
    cudaFuncSetAttribute(out_tc,  cudaFuncAttributeMaxDynamicSharedMemorySize, SMEM_OUT);

    ln_part<<<640, 256>>>(x, Wq, Wk, Wv, Wo);
    norm_x2<<<512, 256, 8192>>>(x);
    qkv_tc<<<dim3(64, 12), 128, SMEM_QKV>>>(bq, bk, bv);
    attn_tc<<<dim3(16, 64), 128, SMEM_ATTN>>>();
    out_tc<<<dim3(128, 2), 256, SMEM_OUT>>>(x, bo, out);
}